// round 5
// baseline (speedup 1.0000x reference)
#include <cuda_runtime.h>
#include <math_constants.h>

#define BN    8
#define BC    256
#define BNF   16
#define BWH   784            // 28*28
#define CSTR  (BNF*BWH)      // 12544 floats between channels
#define CSTR4 (CSTR/4)       // 3136 float4
#define NV4   (BWH/4)        // 196 float4 per (n,f) wh-row
#define NTHR  1024
#define NCG   8              // channel groups in phase 1
#define CPG   (BC/NCG)       // 32 channels per group
#define CPW   4              // channels per warp-pass in phase 3
#define NCACHE 60            // channels cached in smem for phase 3
#define CBASE (BC - NCACHE)  // 196 : first cached channel (multiple of 4)

// dynamic smem layout (floats):
//   scache [NCACHE*BWH] = 47040   (188160 B)
//   part   [NCG*BWH]    =  6272   ( 25088 B)
//   sc     [BWH]        =   784   (  3136 B)
#define SCACHE_F (NCACHE * BWH)
#define PART_F   (NCG * BWH)
#define DYN_F    (SCACHE_F + PART_F + BWH)
#define DYN_B    (DYN_F * 4)

__global__ __launch_bounds__(NTHR, 1)
void mfla_kernel(const float* __restrict__ l,
                 const float* __restrict__ g,
                 const float* __restrict__ w,
                 float* __restrict__ outc,   // [N,NF,W,H]
                 float* __restrict__ outg)   // [N,C,NF]
{
    extern __shared__ __align__(16) float dyn[];
    float* scache = dyn;                     // [60][784]
    float* part   = dyn + SCACHE_F;          // [8][784]
    float* sc     = part + PART_F;           // [784] exp values

    __shared__ float sw[BC];
    __shared__ float red[32];
    __shared__ float s_gdot, s_inv;

    const int tid = threadIdx.x;
    const int n   = blockIdx.x >> 4;
    const int f   = blockIdx.x & 15;
    const float*  lb  = l + ((size_t)n * BC * BNF + f) * BWH;  // lb[c*CSTR + wh]
    const float4* lb4 = reinterpret_cast<const float4*>(lb);

    // ---- weights to smem + gdot = sum_c g[n,c]*w[c] ----
    float p = 0.f;
    if (tid < BC) {
        float wv = w[tid];
        sw[tid] = wv;
        p = g[n * BC + tid] * wv;
    }
    #pragma unroll
    for (int o = 16; o; o >>= 1) p += __shfl_xor_sync(0xffffffffu, p, o);
    if ((tid & 31) == 0) red[tid >> 5] = p;
    __syncthreads();
    if (tid < 32) {
        float v = red[tid];
        #pragma unroll
        for (int o = 16; o; o >>= 1) v += __shfl_xor_sync(0xffffffffu, v, o);
        if (tid == 0) s_gdot = v;
    }
    __syncthreads();

    // ---- Phase 1: partial channel dots (LDG.128); cache tail channels in smem ----
    {
        const int cg = tid >> 7;       // 0..7
        const int wl = tid & 127;      // 0..127
        const int c0 = cg * CPG;
        float4* pv = reinterpret_cast<float4*>(part + cg * BWH);
        for (int i = wl; i < NV4; i += 128) {
            const float4* lp = lb4 + (size_t)c0 * CSTR4 + i;
            float4 a = make_float4(0.f, 0.f, 0.f, 0.f);
            #pragma unroll
            for (int c = 0; c < CPG; ++c) {
                float4 v = lp[(size_t)c * CSTR4];
                const int cc = c0 + c;
                if (cc >= CBASE)    // compile-time resolvable per group after unroll
                    reinterpret_cast<float4*>(scache)[(cc - CBASE) * NV4 + i] = v;
                float wv = sw[cc];
                a.x = fmaf(v.x, wv, a.x);
                a.y = fmaf(v.y, wv, a.y);
                a.z = fmaf(v.z, wv, a.z);
                a.w = fmaf(v.w, wv, a.w);
            }
            pv[i] = a;
        }
    }
    __syncthreads();

    // ---- Phase 1b: combine partials + gdot, write c, exp, partial sum ----
    float se = 0.f;
    if (tid < NV4) {
        const float gd = s_gdot;
        float4 v = make_float4(gd, gd, gd, gd);
        #pragma unroll
        for (int k = 0; k < NCG; ++k) {
            float4 q = reinterpret_cast<const float4*>(part + k * BWH)[tid];
            v.x += q.x; v.y += q.y; v.z += q.z; v.w += q.w;
        }
        reinterpret_cast<float4*>(outc + ((size_t)n * BNF + f) * BWH)[tid] = v;
        float4 e = make_float4(__expf(v.x), __expf(v.y), __expf(v.z), __expf(v.w));
        reinterpret_cast<float4*>(sc)[tid] = e;
        se = (e.x + e.y) + (e.z + e.w);
    }
    // ---- Phase 2: block-reduce the exp-sum ----
    #pragma unroll
    for (int o = 16; o; o >>= 1) se += __shfl_xor_sync(0xffffffffu, se, o);
    if ((tid & 31) == 0) red[tid >> 5] = se;
    __syncthreads();
    if (tid < 32) {
        float v = red[tid];
        #pragma unroll
        for (int o = 16; o; o >>= 1) v += __shfl_xor_sync(0xffffffffu, v, o);
        if (tid == 0) s_inv = 1.0f / v;
    }
    __syncthreads();

    // ---- Phase 3: g_out, 4 ch/warp-pass; tail channels served from smem ----
    {
        const int warp = tid >> 5;
        const int lane = tid & 31;
        const float inv = s_inv;
        const float4* av = reinterpret_cast<const float4*>(sc);
        const float4* cv = reinterpret_cast<const float4*>(scache);
        #pragma unroll
        for (int blk = 0; blk < BC / (32 * CPW); ++blk) {   // 2 passes
            const int c0 = blk * 32 * CPW + warp * CPW;
            float acc[CPW] = {0.f, 0.f, 0.f, 0.f};
            if (c0 >= CBASE) {
                // all 4 channels from smem cache
                const float4* sv = cv + (size_t)(c0 - CBASE) * NV4;
                for (int i = lane; i < NV4; i += 32) {
                    float4 a4 = av[i];
                    #pragma unroll
                    for (int k = 0; k < CPW; ++k) {
                        float4 l4 = sv[(size_t)k * NV4 + i];
                        acc[k] += a4.x * l4.x + a4.y * l4.y + a4.z * l4.z + a4.w * l4.w;
                    }
                }
            } else {
                const float4* lv = lb4 + (size_t)c0 * CSTR4;
                for (int i = lane; i < NV4; i += 32) {
                    float4 a4 = av[i];
                    #pragma unroll
                    for (int k = 0; k < CPW; ++k) {
                        float4 l4 = lv[(size_t)k * CSTR4 + i];
                        acc[k] += a4.x * l4.x + a4.y * l4.y + a4.z * l4.z + a4.w * l4.w;
                    }
                }
            }
            #pragma unroll
            for (int k = 0; k < CPW; ++k) {
                float a = acc[k];
                #pragma unroll
                for (int o = 16; o; o >>= 1) a += __shfl_xor_sync(0xffffffffu, a, o);
                if (lane == 0)
                    outg[((size_t)n * BC + c0 + k) * BNF + f] = a * inv;
            }
        }
    }
}

extern "C" void kernel_launch(void* const* d_in, const int* in_sizes, int n_in,
                              void* d_out, int out_size)
{
    const float* l = (const float*)d_in[0];
    const float* g = (const float*)d_in[1];
    const float* w = (const float*)d_in[2];
    float* out  = (float*)d_out;
    float* outc = out;                              // 8*16*28*28 = 100352 floats
    float* outg = out + (size_t)BN * BNF * BWH;     // 8*256*16   = 32768 floats

    cudaFuncSetAttribute(mfla_kernel,
                         cudaFuncAttributeMaxDynamicSharedMemorySize, DYN_B);
    mfla_kernel<<<BN * BNF, NTHR, DYN_B>>>(l, g, w, outc, outg);
}

// round 6
// speedup vs baseline: 1.0111x; 1.0111x over previous
#include <cuda_runtime.h>
#include <math_constants.h>

#define BN    8
#define BC    256
#define BNF   16
#define BWH   784            // 28*28
#define CSTR  (BNF*BWH)      // 12544 floats between channels
#define CSTR4 (CSTR/4)       // 3136 float4
#define NV4   (BWH/4)        // 196 float4 per (n,f) wh-row
#define NTHR  1024
#define NCG   8              // channel groups in phase 1
#define CPG   (BC/NCG)       // 32 channels per group
#define CPW   4              // channels per warp-pass in phase 3
#define CACHE_PER_G 8        // channels cached per group (c%32 in [24,32))
#define NCACHE (NCG*CACHE_PER_G)   // 64 channels cached

// dynamic smem (floats): scache[64*784]=50176, part[8*784]=6272, sc[784]
#define SCACHE_F (NCACHE * BWH)
#define PART_F   (NCG * BWH)
#define DYN_F    (SCACHE_F + PART_F + BWH)
#define DYN_B    (DYN_F * 4)        // 228,928 B (opt-in)

__global__ __launch_bounds__(NTHR, 1)
void mfla_kernel(const float* __restrict__ l,
                 const float* __restrict__ g,
                 const float* __restrict__ w,
                 float* __restrict__ outc,   // [N,NF,W,H]
                 float* __restrict__ outg)   // [N,C,NF]
{
    extern __shared__ __align__(16) float dyn[];
    float* scache = dyn;                     // [64][784] cached channels
    float* part   = dyn + SCACHE_F;          // [8][784]
    float* sc     = part + PART_F;           // [784] exp values

    __shared__ float sw[BC];
    __shared__ float red[32];
    __shared__ float s_gdot, s_inv;

    const int tid = threadIdx.x;
    const int n   = blockIdx.x >> 4;
    const int f   = blockIdx.x & 15;
    const float*  lb  = l + ((size_t)n * BC * BNF + f) * BWH;  // lb[c*CSTR + wh]
    const float4* lb4 = reinterpret_cast<const float4*>(lb);

    // ---- weights to smem + gdot = sum_c g[n,c]*w[c] ----
    float p = 0.f;
    if (tid < BC) {
        float wv = w[tid];
        sw[tid] = wv;
        p = g[n * BC + tid] * wv;
    }
    #pragma unroll
    for (int o = 16; o; o >>= 1) p += __shfl_xor_sync(0xffffffffu, p, o);
    if ((tid & 31) == 0) red[tid >> 5] = p;
    __syncthreads();
    if (tid < 32) {
        float v = red[tid];
        #pragma unroll
        for (int o = 16; o; o >>= 1) v += __shfl_xor_sync(0xffffffffu, v, o);
        if (tid == 0) s_gdot = v;
    }
    __syncthreads();

    // ---- Phase 1: partial channel dots (LDG.128); cache last 8 ch of EVERY group ----
    {
        const int cg = tid >> 7;       // 0..7
        const int wl = tid & 127;      // 0..127
        const int c0 = cg * CPG;
        float4* pv = reinterpret_cast<float4*>(part + cg * BWH);
        float4* cv = reinterpret_cast<float4*>(scache) + (size_t)cg * CACHE_PER_G * NV4;
        for (int i = wl; i < NV4; i += 128) {
            const float4* lp = lb4 + (size_t)c0 * CSTR4 + i;
            float4 a = make_float4(0.f, 0.f, 0.f, 0.f);
            #pragma unroll
            for (int c = 0; c < CPG; ++c) {
                float4 v = lp[(size_t)c * CSTR4];
                if (c >= CPG - CACHE_PER_G)              // uniform across groups
                    cv[(size_t)(c - (CPG - CACHE_PER_G)) * NV4 + i] = v;
                float wv = sw[c0 + c];
                a.x = fmaf(v.x, wv, a.x);
                a.y = fmaf(v.y, wv, a.y);
                a.z = fmaf(v.z, wv, a.z);
                a.w = fmaf(v.w, wv, a.w);
            }
            pv[i] = a;
        }
    }
    __syncthreads();

    // ---- Phase 1b: combine partials + gdot (784 scalar threads), write c, exp ----
    float se = 0.f;
    if (tid < BWH) {
        float v = s_gdot;
        #pragma unroll
        for (int k = 0; k < NCG; ++k) v += part[k * BWH + tid];
        outc[((size_t)n * BNF + f) * BWH + tid] = v;
        float e = __expf(v);
        sc[tid] = e;
        se = e;
    }
    // ---- Phase 2: block-reduce exp-sum ----
    #pragma unroll
    for (int o = 16; o; o >>= 1) se += __shfl_xor_sync(0xffffffffu, se, o);
    if ((tid & 31) == 0) red[tid >> 5] = se;
    __syncthreads();
    if (tid < 32) {
        float v = red[tid];
        #pragma unroll
        for (int o = 16; o; o >>= 1) v += __shfl_xor_sync(0xffffffffu, v, o);
        if (tid == 0) s_inv = 1.0f / v;
    }
    __syncthreads();

    // ---- Phase 3: g_out, 4 ch/warp-pass; c%32 in [24,32) served from smem ----
    {
        const int warp = tid >> 5;
        const int lane = tid & 31;
        const float inv = s_inv;
        const float4* av  = reinterpret_cast<const float4*>(sc);
        const float4* scv = reinterpret_cast<const float4*>(scache);
        #pragma unroll
        for (int blk = 0; blk < BC / (32 * CPW); ++blk) {   // 2 passes
            const int c0 = blk * 32 * CPW + warp * CPW;
            float acc[CPW] = {0.f, 0.f, 0.f, 0.f};
            if ((c0 & 31) >= CPG - CACHE_PER_G) {
                // cached block: group = c0/32, slot = c0%32 - 24
                const float4* sv = scv +
                    (size_t)((c0 >> 5) * CACHE_PER_G + (c0 & 31) - (CPG - CACHE_PER_G)) * NV4;
                for (int i = lane; i < NV4; i += 32) {
                    float4 a4 = av[i];
                    #pragma unroll
                    for (int k = 0; k < CPW; ++k) {
                        float4 l4 = sv[(size_t)k * NV4 + i];
                        acc[k] += a4.x * l4.x + a4.y * l4.y + a4.z * l4.z + a4.w * l4.w;
                    }
                }
            } else {
                const float4* lv = lb4 + (size_t)c0 * CSTR4;
                for (int i = lane; i < NV4; i += 32) {
                    float4 a4 = av[i];
                    #pragma unroll
                    for (int k = 0; k < CPW; ++k) {
                        float4 l4 = lv[(size_t)k * CSTR4 + i];
                        acc[k] += a4.x * l4.x + a4.y * l4.y + a4.z * l4.z + a4.w * l4.w;
                    }
                }
            }
            #pragma unroll
            for (int k = 0; k < CPW; ++k) {
                float a = acc[k];
                #pragma unroll
                for (int o = 16; o; o >>= 1) a += __shfl_xor_sync(0xffffffffu, a, o);
                if (lane == 0)
                    outg[((size_t)n * BC + c0 + k) * BNF + f] = a * inv;
            }
        }
    }
}

extern "C" void kernel_launch(void* const* d_in, const int* in_sizes, int n_in,
                              void* d_out, int out_size)
{
    const float* l = (const float*)d_in[0];
    const float* g = (const float*)d_in[1];
    const float* w = (const float*)d_in[2];
    float* out  = (float*)d_out;
    float* outc = out;                              // 8*16*28*28 = 100352 floats
    float* outg = out + (size_t)BN * BNF * BWH;     // 8*256*16   = 32768 floats

    cudaFuncSetAttribute(mfla_kernel,
                         cudaFuncAttributeMaxDynamicSharedMemorySize, DYN_B);
    mfla_kernel<<<BN * BNF, NTHR, DYN_B>>>(l, g, w, outc, outg);
}